// round 11
// baseline (speedup 1.0000x reference)
#include <cuda_runtime.h>
#include <cuda_fp16.h>
#include <cstdint>

#define NV    514
#define SDIM  512
#define MROWS 65536
#define EPSF  1e-16f

// ---------------------------------------------------------------------------
// Device scratch.
// g_B: R^T rows as fp16, PRE-SWIZZLED SMEM tile images:
//      [ntile(4)][chunk(8)] x 16384 B; each = 128(n) x 64(k) fp16, SW128.
// g_P: pairwise reflector dots (quad Gram terms + tail pair).
// ---------------------------------------------------------------------------
__device__ __align__(16) unsigned char g_B[4 * 8 * 16384];
__device__ float g_c[NV];
__device__ float g_P[769];

#define SW128(b) ((b) ^ (((b) >> 3) & 0x70))
#define PAIR_DOTS 769
#define PAIR_BLOCKS 97

__device__ __forceinline__ uint32_t smem_u32(const void* p) {
    uint32_t a;
    asm("{ .reg .u64 t; cvta.to.shared.u64 t, %1; cvt.u32.u64 %0, t; }"
        : "=r"(a) : "l"(p));
    return a;
}

// ===========================================================================
// Kernel 1 (small, all-parallel): c_k | quad pairwise dots
// ===========================================================================
__global__ __launch_bounds__(256) void c_pair_kernel(const float* __restrict__ v) {
    if (blockIdx.x < NV) {
        const int k = blockIdx.x;
        const int t = threadIdx.x;
        const float2 e = ((const float2*)(v + k * SDIM))[t];
        float s = fmaf(e.x, e.x, e.y * e.y);
        #pragma unroll
        for (int o = 16; o > 0; o >>= 1) s += __shfl_xor_sync(0xffffffffu, s, o);
        __shared__ float red[8];
        if ((t & 31) == 0) red[t >> 5] = s;
        __syncthreads();
        if (t == 0) {
            float tot = 0.f;
            #pragma unroll
            for (int i = 0; i < 8; ++i) tot += red[i];
            g_c[k] = 2.0f / (tot + EPSF);
        }
        return;
    }
    // ---- pairwise dots: one warp per dot ----
    const int pb = blockIdx.x - NV;
    const int w = threadIdx.x >> 5;
    const int lane = threadIdx.x & 31;
    const int D = pb * 8 + w;
    if (D >= PAIR_DOTS) return;
    int ka, kb;
    if (D == 768) { ka = 513; kb = 512; }
    else {
        const int iq = D / 6, rr = D % 6;
        const int i_of[6] = {1, 2, 2, 3, 3, 3};
        const int j_of[6] = {0, 0, 1, 0, 1, 2};
        ka = 4 * iq + i_of[rr];
        kb = 4 * iq + j_of[rr];
    }
    const float4* pa = (const float4*)(v + (size_t)ka * SDIM);
    const float4* pc = (const float4*)(v + (size_t)kb * SDIM);
    float s = 0.f;
    #pragma unroll
    for (int m = 0; m < 4; ++m) {
        float4 fa = pa[m * 32 + lane];
        float4 fb = pc[m * 32 + lane];
        s = fmaf(fa.x, fb.x, s); s = fmaf(fa.y, fb.y, s);
        s = fmaf(fa.z, fb.z, s); s = fmaf(fa.w, fb.w, s);
    }
    #pragma unroll
    for (int o = 16; o > 0; o >>= 1) s += __shfl_xor_sync(0xffffffffu, s, o);
    if (lane == 0) g_P[D] = s;
}

// ===========================================================================
// Kernel 2: reflector chain, 4 reflectors per iteration (block Householder).
// One warp per column j; emits fp16 pre-swizzled rows of R^T.
// ===========================================================================
__global__ __launch_bounds__(256) void build_R_kernel(const float* __restrict__ v) {
    __shared__ float sc[NV];
    __shared__ float sp[PAIR_DOTS];
    for (int i = threadIdx.x; i < NV; i += blockDim.x) sc[i] = g_c[i];
    for (int i = threadIdx.x; i < PAIR_DOTS; i += blockDim.x) sp[i] = g_P[i];
    __syncthreads();

    const int lane = threadIdx.x & 31;
    const int j = blockIdx.x * 8 + (threadIdx.x >> 5);

    float r[16];
    #pragma unroll
    for (int i = 0; i < 16; ++i) r[i] = 0.f;
    {
        const int m = j >> 7;
        if (lane == ((j & 127) >> 2)) r[m * 4 + (j & 3)] = 1.0f;
    }

    const float4* v4 = (const float4*)v;
    float a[4][16], an[4][16];
    #pragma unroll
    for (int i = 0; i < 4; ++i)
        #pragma unroll
        for (int m = 0; m < 4; ++m) {
            float4 t = v4[(size_t)i * 128 + m * 32 + lane];
            a[i][m*4+0]=t.x; a[i][m*4+1]=t.y; a[i][m*4+2]=t.z; a[i][m*4+3]=t.w;
        }

    for (int w = 0; w < 128; ++w) {
        const int k0 = w * 4;
        float dA[4], dB[4];
        #pragma unroll
        for (int i = 0; i < 4; ++i) { dA[i] = 0.f; dB[i] = 0.f; }
        #pragma unroll
        for (int e = 0; e < 16; e += 2) {
            #pragma unroll
            for (int i = 0; i < 4; ++i) {
                dA[i] = fmaf(a[i][e],   r[e],   dA[i]);
                dB[i] = fmaf(a[i][e+1], r[e+1], dB[i]);
            }
        }
        if (w < 127) {
            #pragma unroll
            for (int i = 0; i < 4; ++i)
                #pragma unroll
                for (int m = 0; m < 4; ++m) {
                    float4 t = v4[(size_t)(k0 + 4 + i) * 128 + m * 32 + lane];
                    an[i][m*4+0]=t.x; an[i][m*4+1]=t.y; an[i][m*4+2]=t.z; an[i][m*4+3]=t.w;
                }
        } else {
            #pragma unroll
            for (int i = 0; i < 2; ++i)
                #pragma unroll
                for (int m = 0; m < 4; ++m) {
                    float4 t = v4[(size_t)(512 + i) * 128 + m * 32 + lane];
                    an[i][m*4+0]=t.x; an[i][m*4+1]=t.y; an[i][m*4+2]=t.z; an[i][m*4+3]=t.w;
                }
        }
        float d0 = dA[0]+dB[0], d1 = dA[1]+dB[1], d2 = dA[2]+dB[2], d3 = dA[3]+dB[3];
        #pragma unroll
        for (int o = 16; o > 0; o >>= 1) {
            d0 += __shfl_xor_sync(0xffffffffu, d0, o);
            d1 += __shfl_xor_sync(0xffffffffu, d1, o);
            d2 += __shfl_xor_sync(0xffffffffu, d2, o);
            d3 += __shfl_xor_sync(0xffffffffu, d3, o);
        }
        const float* P = sp + w * 6;
        const float t0 = d0 * sc[k0];
        const float t1 = fmaf(-t0, P[0], d1) * sc[k0+1];
        const float t2 = fmaf(-t1, P[2], fmaf(-t0, P[1], d2)) * sc[k0+2];
        const float t3 = fmaf(-t2, P[5], fmaf(-t1, P[4], fmaf(-t0, P[3], d3))) * sc[k0+3];
        #pragma unroll
        for (int e = 0; e < 16; ++e)
            r[e] = fmaf(-t3, a[3][e],
                   fmaf(-t2, a[2][e],
                   fmaf(-t1, a[1][e],
                   fmaf(-t0, a[0][e], r[e]))));
        #pragma unroll
        for (int i = 0; i < 4; ++i)
            #pragma unroll
            for (int e = 0; e < 16; ++e) a[i][e] = an[i][e];
    }

    {   // tail: reflectors 512, 513
        float dA0=0.f, dB0=0.f, dA1=0.f, dB1=0.f;
        #pragma unroll
        for (int e = 0; e < 16; e += 2) {
            dA0 = fmaf(a[0][e],   r[e],   dA0);
            dB0 = fmaf(a[0][e+1], r[e+1], dB0);
            dA1 = fmaf(a[1][e],   r[e],   dA1);
            dB1 = fmaf(a[1][e+1], r[e+1], dB1);
        }
        float d = dA0 + dB0, p = dA1 + dB1;
        #pragma unroll
        for (int o = 16; o > 0; o >>= 1) {
            d += __shfl_xor_sync(0xffffffffu, d, o);
            p += __shfl_xor_sync(0xffffffffu, p, o);
        }
        const float q  = sp[768];
        const float t0 = d * sc[512];
        const float t1 = fmaf(-t0, q, p) * sc[513];
        #pragma unroll
        for (int e = 0; e < 16; ++e)
            r[e] = fmaf(-t1, a[1][e], fmaf(-t0, a[0][e], r[e]));
    }

    const int ntile = j >> 7;
    const unsigned rowb = (unsigned)(j & 127) * 128u;
    #pragma unroll
    for (int m = 0; m < 4; ++m) {
        const int k0 = m * 128 + lane * 4;
        const int chunk = k0 >> 6;
        const unsigned off = rowb + (unsigned)((k0 & 63) * 2);
        const unsigned sw = SW128(off);
        __half2 p0 = __floats2half2_rn(r[m*4+0], r[m*4+1]);
        __half2 p1 = __floats2half2_rn(r[m*4+2], r[m*4+3]);
        uint2 H = make_uint2(*(uint32_t*)&p0, *(uint32_t*)&p1);
        *(uint2*)(g_B + (((size_t)ntile*8 + chunk) * 16384) + sw) = H;
    }
}

// ===========================================================================
// Kernel 3: out = x @ R via mma.sync fp16 (fp32 acc).
// CTA 128x128, 8 warps (4m x 2n), warp 32x64, K-chunk 64, 3 stages,
// 2 CTAs/SM. A converted fp32->fp16 IN-LOOP (LDG+cvt+STS hidden in the
// 2-stage pipeline slack); B via cp.async from pre-swizzled g_B.
// ===========================================================================
#define A_OFF 0
#define B_OFF 16384
#define STAGE_BYTES 32768
#define NSTAGE 3
#define GEMM_SMEM (1024 + NSTAGE * STAGE_BYTES)

__device__ __forceinline__ void ldsm4(uint32_t* r, uint32_t addr) {
    asm volatile("ldmatrix.sync.aligned.m8n8.x4.shared.b16 {%0,%1,%2,%3}, [%4];"
        : "=r"(r[0]), "=r"(r[1]), "=r"(r[2]), "=r"(r[3]) : "r"(addr));
}
__device__ __forceinline__ void mma16816(float* c, const uint32_t* a,
                                         uint32_t b0, uint32_t b1) {
    asm volatile(
        "mma.sync.aligned.m16n8k16.row.col.f32.f16.f16.f32 "
        "{%0,%1,%2,%3}, {%4,%5,%6,%7}, {%8,%9}, {%0,%1,%2,%3};"
        : "+f"(c[0]), "+f"(c[1]), "+f"(c[2]), "+f"(c[3])
        : "r"(a[0]), "r"(a[1]), "r"(a[2]), "r"(a[3]), "r"(b0), "r"(b1));
}
__device__ __forceinline__ void cpasync16(uint32_t dst, const void* src) {
    asm volatile("cp.async.cg.shared.global [%0], [%1], 16;"
        :: "r"(dst), "l"(src) : "memory");
}
#define CP_COMMIT() asm volatile("cp.async.commit_group;" ::: "memory")
#define CP_WAIT(n)  asm volatile("cp.async.wait_group %0;" :: "n"(n) : "memory")

__global__ __launch_bounds__(256, 2) void gemm_mma_kernel(const float* __restrict__ x,
                                                          float* __restrict__ out) {
    extern __shared__ char dsm[];
    char* smp = (char*)(((uintptr_t)dsm + 1023) & ~(uintptr_t)1023);
    const uint32_t sb = smem_u32(smp);

    const int tid = threadIdx.x;
    const int wid = tid >> 5;
    const int lane = tid & 31;
    const int wm = wid & 3;          // m offset wm*32
    const int wn = wid >> 2;         // n offset wn*64
    const int nt = blockIdx.x;       // 0..3
    const int bm = blockIdx.y << 7;
    const int bn = nt << 7;

    // A fill addressing: thread -> (row, k-half of 32 floats)
    const int arow = tid >> 1;
    const int ahalf = tid & 1;                       // 0/1 -> k-sub [0,32)/[32,64)
    const float* xRow = x + (size_t)(bm + arow) * SDIM + ahalf * 32;
    const unsigned aBase = (unsigned)arow * 128u + (unsigned)ahalf * 64u;

    float c[2][8][4];
    #pragma unroll
    for (int i = 0; i < 2; ++i)
        #pragma unroll
        for (int jj = 0; jj < 8; ++jj)
            #pragma unroll
            for (int q = 0; q < 4; ++q) c[i][jj][q] = 0.f;

    // B: cp.async of pre-swizzled image; A: LDG fp32 -> cvt -> STS swizzled
    auto fill_stage = [&](int kc) {
        const uint32_t st = sb + (kc % NSTAGE) * STAGE_BYTES;
        const char* bSrc = (const char*)(g_B + (((size_t)nt * 8 + kc) * 16384)) + tid * 16;
        #pragma unroll
        for (int i = 0; i < 4; ++i)
            cpasync16(st + B_OFF + tid * 16 + i * 4096, bSrc + i * 4096);
        CP_COMMIT();
        const float4* aSrc = (const float4*)(xRow + kc * 64);
        char* ab = smp + (st - sb) + A_OFF;
        #pragma unroll
        for (int i = 0; i < 4; ++i) {
            float4 f0 = aSrc[2*i], f1 = aSrc[2*i+1];
            __half2 h0 = __floats2half2_rn(f0.x, f0.y);
            __half2 h1 = __floats2half2_rn(f0.z, f0.w);
            __half2 h2 = __floats2half2_rn(f1.x, f1.y);
            __half2 h3 = __floats2half2_rn(f1.z, f1.w);
            uint4 hv = make_uint4(*(uint32_t*)&h0, *(uint32_t*)&h1,
                                  *(uint32_t*)&h2, *(uint32_t*)&h3);
            *(uint4*)(ab + SW128(aBase + i * 16u)) = hv;
        }
    };

    fill_stage(0);
    fill_stage(1);

    const int la = lane & 15;
    const int lh = lane >> 4;

    for (int kc = 0; kc < 8; ++kc) {
        if (kc == 7) { CP_WAIT(0); } else { CP_WAIT(1); }
        __syncthreads();   // stage kc (cp.async B + STS A) visible; (kc-1)%3 free
        if (kc < 6) fill_stage(kc + 2);

        const uint32_t st = sb + (kc % NSTAGE) * STAGE_BYTES;
        #pragma unroll
        for (int ks = 0; ks < 4; ++ks) {
            uint32_t af[2][4], bf[4][4];
            #pragma unroll
            for (int mt = 0; mt < 2; ++mt) {
                const unsigned off = (unsigned)(wm*32 + mt*16 + la) * 128u
                                   + (unsigned)((lh*8 + ks*16) * 2);
                ldsm4(af[mt], st + A_OFF + SW128(off));
            }
            #pragma unroll
            for (int np = 0; np < 4; ++np) {
                const unsigned off = (unsigned)(wn*64 + np*16 + la) * 128u
                                   + (unsigned)((lh*8 + ks*16) * 2);
                ldsm4(bf[np], st + B_OFF + SW128(off));
            }
            #pragma unroll
            for (int mt = 0; mt < 2; ++mt)
                #pragma unroll
                for (int np = 0; np < 4; ++np) {
                    mma16816(c[mt][2*np],   af[mt], bf[np][0], bf[np][2]);
                    mma16816(c[mt][2*np+1], af[mt], bf[np][1], bf[np][3]);
                }
        }
    }

    // epilogue
    const int r0 = bm + wm * 32 + (lane >> 2);
    const int c0 = bn + wn * 64 + (lane & 3) * 2;
    #pragma unroll
    for (int mt = 0; mt < 2; ++mt) {
        #pragma unroll
        for (int ntl = 0; ntl < 8; ++ntl) {
            float* p0 = out + (size_t)(r0 + mt*16)     * SDIM + c0 + ntl*8;
            float* p1 = out + (size_t)(r0 + mt*16 + 8) * SDIM + c0 + ntl*8;
            *(float2*)p0 = make_float2(c[mt][ntl][0], c[mt][ntl][1]);
            *(float2*)p1 = make_float2(c[mt][ntl][2], c[mt][ntl][3]);
        }
    }
}

// ===========================================================================
extern "C" void kernel_launch(void* const* d_in, const int* in_sizes, int n_in,
                              void* d_out, int out_size) {
    const float* x = (const float*)d_in[0];   // [65536, 512]
    const float* v = (const float*)d_in[1];   // [514, 512, 1]
    float* out = (float*)d_out;               // [65536, 512]

    cudaFuncSetAttribute(gemm_mma_kernel, cudaFuncAttributeMaxDynamicSharedMemorySize, GEMM_SMEM);

    c_pair_kernel<<<NV + PAIR_BLOCKS, 256>>>(v);
    build_R_kernel<<<64, 256>>>(v);
    dim3 grid(4, MROWS / 128);
    gemm_mma_kernel<<<grid, 256, GEMM_SMEM>>>(x, out);
}

// round 12
// speedup vs baseline: 1.3128x; 1.3128x over previous
#include <cuda_runtime.h>
#include <cuda_fp16.h>
#include <cstdint>

#define NV    514
#define SDIM  512
#define MROWS 65536
#define EPSF  1e-16f

// ---------------------------------------------------------------------------
// Device scratch.
// g_B: R^T rows as fp16, PRE-SWIZZLED SMEM tile images:
//      [ntile(4)][chunk(8)] x 16384 B; each = 128(n) x 64(k) fp16, SW128.
// g_X: x converted to fp16, row-major [65536][512].
// g_P: pairwise reflector dots (quad Gram terms + tail pair).
// ---------------------------------------------------------------------------
__device__ __align__(16) unsigned char g_B[4 * 8 * 16384];
__device__ __align__(16) __half g_X[(size_t)MROWS * SDIM];
__device__ float g_c[NV];
__device__ float g_P[769];

#define SW128(b) ((b) ^ (((b) >> 3) & 0x70))
#define PAIR_DOTS 769
#define PAIR_BLOCKS 97
#define CVT_BLOCKS 8192

__device__ __forceinline__ uint32_t smem_u32(const void* p) {
    uint32_t a;
    asm("{ .reg .u64 t; cvta.to.shared.u64 t, %1; cvt.u32.u64 %0, t; }"
        : "=r"(a) : "l"(p));
    return a;
}

// ===========================================================================
// Kernel 1 (all-parallel): convert x -> fp16 | c_k | quad pairwise dots
// ===========================================================================
__global__ __launch_bounds__(256) void cvt_c_kernel(const float* __restrict__ x,
                                                    const float* __restrict__ v) {
    if (blockIdx.x < CVT_BLOCKS) {
        const size_t g = ((size_t)blockIdx.x * 256 + threadIdx.x) * 16;
        const float4* src = (const float4*)(x + g);
        float4 f0 = src[0], f1 = src[1], f2 = src[2], f3 = src[3];
        __half2 h[8];
        h[0] = __floats2half2_rn(f0.x, f0.y); h[1] = __floats2half2_rn(f0.z, f0.w);
        h[2] = __floats2half2_rn(f1.x, f1.y); h[3] = __floats2half2_rn(f1.z, f1.w);
        h[4] = __floats2half2_rn(f2.x, f2.y); h[5] = __floats2half2_rn(f2.z, f2.w);
        h[6] = __floats2half2_rn(f3.x, f3.y); h[7] = __floats2half2_rn(f3.z, f3.w);
        uint4* dst = (uint4*)(g_X + g);
        dst[0] = make_uint4(*(uint32_t*)&h[0], *(uint32_t*)&h[1],
                            *(uint32_t*)&h[2], *(uint32_t*)&h[3]);
        dst[1] = make_uint4(*(uint32_t*)&h[4], *(uint32_t*)&h[5],
                            *(uint32_t*)&h[6], *(uint32_t*)&h[7]);
        return;
    }
    if (blockIdx.x < CVT_BLOCKS + NV) {
        const int k = blockIdx.x - CVT_BLOCKS;
        const int t = threadIdx.x;
        const float2 e = ((const float2*)(v + k * SDIM))[t];
        float s = fmaf(e.x, e.x, e.y * e.y);
        #pragma unroll
        for (int o = 16; o > 0; o >>= 1) s += __shfl_xor_sync(0xffffffffu, s, o);
        __shared__ float red[8];
        if ((t & 31) == 0) red[t >> 5] = s;
        __syncthreads();
        if (t == 0) {
            float tot = 0.f;
            #pragma unroll
            for (int i = 0; i < 8; ++i) tot += red[i];
            g_c[k] = 2.0f / (tot + EPSF);
        }
        return;
    }
    // ---- pairwise dots: one warp per dot ----
    const int pb = blockIdx.x - CVT_BLOCKS - NV;
    const int w = threadIdx.x >> 5;
    const int lane = threadIdx.x & 31;
    const int D = pb * 8 + w;
    if (D >= PAIR_DOTS) return;
    int ka, kb;
    if (D == 768) { ka = 513; kb = 512; }
    else {
        const int iq = D / 6, rr = D % 6;
        const int i_of[6] = {1, 2, 2, 3, 3, 3};
        const int j_of[6] = {0, 0, 1, 0, 1, 2};
        ka = 4 * iq + i_of[rr];
        kb = 4 * iq + j_of[rr];
    }
    const float4* pa = (const float4*)(v + (size_t)ka * SDIM);
    const float4* pc = (const float4*)(v + (size_t)kb * SDIM);
    float s = 0.f;
    #pragma unroll
    for (int m = 0; m < 4; ++m) {
        float4 fa = pa[m * 32 + lane];
        float4 fb = pc[m * 32 + lane];
        s = fmaf(fa.x, fb.x, s); s = fmaf(fa.y, fb.y, s);
        s = fmaf(fa.z, fb.z, s); s = fmaf(fa.w, fb.w, s);
    }
    #pragma unroll
    for (int o = 16; o > 0; o >>= 1) s += __shfl_xor_sync(0xffffffffu, s, o);
    if (lane == 0) g_P[D] = s;
}

// ===========================================================================
// Kernel 2: reflector chain, 4 reflectors per iteration (block Householder).
// One warp per column j; emits fp16 pre-swizzled rows of R^T.
// ===========================================================================
__global__ __launch_bounds__(256) void build_R_kernel(const float* __restrict__ v) {
    __shared__ float sc[NV];
    __shared__ float sp[PAIR_DOTS];
    for (int i = threadIdx.x; i < NV; i += blockDim.x) sc[i] = g_c[i];
    for (int i = threadIdx.x; i < PAIR_DOTS; i += blockDim.x) sp[i] = g_P[i];
    __syncthreads();

    const int lane = threadIdx.x & 31;
    const int j = blockIdx.x * 8 + (threadIdx.x >> 5);

    float r[16];
    #pragma unroll
    for (int i = 0; i < 16; ++i) r[i] = 0.f;
    {
        const int m = j >> 7;
        if (lane == ((j & 127) >> 2)) r[m * 4 + (j & 3)] = 1.0f;
    }

    const float4* v4 = (const float4*)v;
    float a[4][16], an[4][16];
    #pragma unroll
    for (int i = 0; i < 4; ++i)
        #pragma unroll
        for (int m = 0; m < 4; ++m) {
            float4 t = v4[(size_t)i * 128 + m * 32 + lane];
            a[i][m*4+0]=t.x; a[i][m*4+1]=t.y; a[i][m*4+2]=t.z; a[i][m*4+3]=t.w;
        }

    for (int w = 0; w < 128; ++w) {
        const int k0 = w * 4;
        float dA[4], dB[4];
        #pragma unroll
        for (int i = 0; i < 4; ++i) { dA[i] = 0.f; dB[i] = 0.f; }
        #pragma unroll
        for (int e = 0; e < 16; e += 2) {
            #pragma unroll
            for (int i = 0; i < 4; ++i) {
                dA[i] = fmaf(a[i][e],   r[e],   dA[i]);
                dB[i] = fmaf(a[i][e+1], r[e+1], dB[i]);
            }
        }
        if (w < 127) {
            #pragma unroll
            for (int i = 0; i < 4; ++i)
                #pragma unroll
                for (int m = 0; m < 4; ++m) {
                    float4 t = v4[(size_t)(k0 + 4 + i) * 128 + m * 32 + lane];
                    an[i][m*4+0]=t.x; an[i][m*4+1]=t.y; an[i][m*4+2]=t.z; an[i][m*4+3]=t.w;
                }
        } else {
            #pragma unroll
            for (int i = 0; i < 2; ++i)
                #pragma unroll
                for (int m = 0; m < 4; ++m) {
                    float4 t = v4[(size_t)(512 + i) * 128 + m * 32 + lane];
                    an[i][m*4+0]=t.x; an[i][m*4+1]=t.y; an[i][m*4+2]=t.z; an[i][m*4+3]=t.w;
                }
        }
        float d0 = dA[0]+dB[0], d1 = dA[1]+dB[1], d2 = dA[2]+dB[2], d3 = dA[3]+dB[3];
        #pragma unroll
        for (int o = 16; o > 0; o >>= 1) {
            d0 += __shfl_xor_sync(0xffffffffu, d0, o);
            d1 += __shfl_xor_sync(0xffffffffu, d1, o);
            d2 += __shfl_xor_sync(0xffffffffu, d2, o);
            d3 += __shfl_xor_sync(0xffffffffu, d3, o);
        }
        const float* P = sp + w * 6;
        const float t0 = d0 * sc[k0];
        const float t1 = fmaf(-t0, P[0], d1) * sc[k0+1];
        const float t2 = fmaf(-t1, P[2], fmaf(-t0, P[1], d2)) * sc[k0+2];
        const float t3 = fmaf(-t2, P[5], fmaf(-t1, P[4], fmaf(-t0, P[3], d3))) * sc[k0+3];
        #pragma unroll
        for (int e = 0; e < 16; ++e)
            r[e] = fmaf(-t3, a[3][e],
                   fmaf(-t2, a[2][e],
                   fmaf(-t1, a[1][e],
                   fmaf(-t0, a[0][e], r[e]))));
        #pragma unroll
        for (int i = 0; i < 4; ++i)
            #pragma unroll
            for (int e = 0; e < 16; ++e) a[i][e] = an[i][e];
    }

    {   // tail: reflectors 512, 513
        float dA0=0.f, dB0=0.f, dA1=0.f, dB1=0.f;
        #pragma unroll
        for (int e = 0; e < 16; e += 2) {
            dA0 = fmaf(a[0][e],   r[e],   dA0);
            dB0 = fmaf(a[0][e+1], r[e+1], dB0);
            dA1 = fmaf(a[1][e],   r[e],   dA1);
            dB1 = fmaf(a[1][e+1], r[e+1], dB1);
        }
        float d = dA0 + dB0, p = dA1 + dB1;
        #pragma unroll
        for (int o = 16; o > 0; o >>= 1) {
            d += __shfl_xor_sync(0xffffffffu, d, o);
            p += __shfl_xor_sync(0xffffffffu, p, o);
        }
        const float q  = sp[768];
        const float t0 = d * sc[512];
        const float t1 = fmaf(-t0, q, p) * sc[513];
        #pragma unroll
        for (int e = 0; e < 16; ++e)
            r[e] = fmaf(-t1, a[1][e], fmaf(-t0, a[0][e], r[e]));
    }

    const int ntile = j >> 7;
    const unsigned rowb = (unsigned)(j & 127) * 128u;
    #pragma unroll
    for (int m = 0; m < 4; ++m) {
        const int k0 = m * 128 + lane * 4;
        const int chunk = k0 >> 6;
        const unsigned off = rowb + (unsigned)((k0 & 63) * 2);
        const unsigned sw = SW128(off);
        __half2 p0 = __floats2half2_rn(r[m*4+0], r[m*4+1]);
        __half2 p1 = __floats2half2_rn(r[m*4+2], r[m*4+3]);
        uint2 H = make_uint2(*(uint32_t*)&p0, *(uint32_t*)&p1);
        *(uint2*)(g_B + (((size_t)ntile*8 + chunk) * 16384) + sw) = H;
    }
}

// ===========================================================================
// Kernel 3: out = x @ R via mma.sync fp16 (fp32 acc), pure cp.async pipeline.
// CTA 128x128, 8 warps (4m x 2n), warp 32x64, K-chunk 64, 3 stages,
// 2 CTAs/SM, one __syncthreads/iter, FULLY UNROLLED mainloop,
// streaming (evict-first) epilogue stores.
// ===========================================================================
#define A_OFF 0
#define B_OFF 16384
#define STAGE_BYTES 32768
#define NSTAGE 3
#define GEMM_SMEM (1024 + NSTAGE * STAGE_BYTES)

__device__ __forceinline__ void ldsm4(uint32_t* r, uint32_t addr) {
    asm volatile("ldmatrix.sync.aligned.m8n8.x4.shared.b16 {%0,%1,%2,%3}, [%4];"
        : "=r"(r[0]), "=r"(r[1]), "=r"(r[2]), "=r"(r[3]) : "r"(addr));
}
__device__ __forceinline__ void mma16816(float* c, const uint32_t* a,
                                         uint32_t b0, uint32_t b1) {
    asm volatile(
        "mma.sync.aligned.m16n8k16.row.col.f32.f16.f16.f32 "
        "{%0,%1,%2,%3}, {%4,%5,%6,%7}, {%8,%9}, {%0,%1,%2,%3};"
        : "+f"(c[0]), "+f"(c[1]), "+f"(c[2]), "+f"(c[3])
        : "r"(a[0]), "r"(a[1]), "r"(a[2]), "r"(a[3]), "r"(b0), "r"(b1));
}
__device__ __forceinline__ void cpasync16(uint32_t dst, const void* src) {
    asm volatile("cp.async.cg.shared.global [%0], [%1], 16;"
        :: "r"(dst), "l"(src) : "memory");
}
#define CP_COMMIT() asm volatile("cp.async.commit_group;" ::: "memory")
#define CP_WAIT(n)  asm volatile("cp.async.wait_group %0;" :: "n"(n) : "memory")

__device__ __forceinline__ void stcs2(float* p, float a, float b) {
    asm volatile("st.global.cs.v2.f32 [%0], {%1, %2};" :: "l"(p), "f"(a), "f"(b) : "memory");
}

__global__ __launch_bounds__(256, 2) void gemm_mma_kernel(float* __restrict__ out) {
    extern __shared__ char dsm[];
    char* smp = (char*)(((uintptr_t)dsm + 1023) & ~(uintptr_t)1023);
    const uint32_t sb = smem_u32(smp);

    const int tid = threadIdx.x;
    const int wid = tid >> 5;
    const int lane = tid & 31;
    const int wm = wid & 3;          // m offset wm*32
    const int wn = wid >> 2;         // n offset wn*64
    const int nt = blockIdx.x;       // 0..3
    const int bm = blockIdx.y << 7;
    const int bn = nt << 7;

    const int arow = tid >> 1;
    const int ahalf = (tid & 1) * 64;
    const __half* aRowPtr = g_X + (size_t)(bm + arow) * SDIM;
    const unsigned aBase = (unsigned)arow * 128u + (unsigned)ahalf;

    float c[2][8][4];
    #pragma unroll
    for (int i = 0; i < 2; ++i)
        #pragma unroll
        for (int jj = 0; jj < 8; ++jj)
            #pragma unroll
            for (int q = 0; q < 4; ++q) c[i][jj][q] = 0.f;

    auto fill_stage = [&](int kc) {
        const uint32_t st = sb + (kc % NSTAGE) * STAGE_BYTES;
        const char* aSrc = (const char*)(aRowPtr + kc * 64) + ahalf;
        #pragma unroll
        for (int i = 0; i < 4; ++i)
            cpasync16(st + A_OFF + SW128(aBase + i * 16u), aSrc + i * 16);
        const char* bSrc = (const char*)(g_B + (((size_t)nt * 8 + kc) * 16384)) + tid * 16;
        #pragma unroll
        for (int i = 0; i < 4; ++i)
            cpasync16(st + B_OFF + tid * 16 + i * 4096, bSrc + i * 4096);
        CP_COMMIT();
    };

    fill_stage(0);
    fill_stage(1);

    const int la = lane & 15;
    const int lh = lane >> 4;

    #pragma unroll
    for (int kc = 0; kc < 8; ++kc) {
        if (kc == 7) { CP_WAIT(0); } else { CP_WAIT(1); }
        __syncthreads();   // stage kc visible; stage (kc-1)%3 fully consumed
        if (kc < 6) fill_stage(kc + 2);

        const uint32_t st = sb + (kc % NSTAGE) * STAGE_BYTES;
        #pragma unroll
        for (int ks = 0; ks < 4; ++ks) {
            uint32_t af[2][4], bf[4][4];
            #pragma unroll
            for (int mt = 0; mt < 2; ++mt) {
                const unsigned off = (unsigned)(wm*32 + mt*16 + la) * 128u
                                   + (unsigned)((lh*8 + ks*16) * 2);
                ldsm4(af[mt], st + A_OFF + SW128(off));
            }
            #pragma unroll
            for (int np = 0; np < 4; ++np) {
                const unsigned off = (unsigned)(wn*64 + np*16 + la) * 128u
                                   + (unsigned)((lh*8 + ks*16) * 2);
                ldsm4(bf[np], st + B_OFF + SW128(off));
            }
            #pragma unroll
            for (int mt = 0; mt < 2; ++mt)
                #pragma unroll
                for (int np = 0; np < 4; ++np) {
                    mma16816(c[mt][2*np],   af[mt], bf[np][0], bf[np][2]);
                    mma16816(c[mt][2*np+1], af[mt], bf[np][1], bf[np][3]);
                }
        }
    }

    // epilogue (streaming stores — out is write-once, keep L2 for g_X/g_B)
    const int r0 = bm + wm * 32 + (lane >> 2);
    const int c0 = bn + wn * 64 + (lane & 3) * 2;
    #pragma unroll
    for (int mt = 0; mt < 2; ++mt) {
        #pragma unroll
        for (int ntl = 0; ntl < 8; ++ntl) {
            float* p0 = out + (size_t)(r0 + mt*16)     * SDIM + c0 + ntl*8;
            float* p1 = out + (size_t)(r0 + mt*16 + 8) * SDIM + c0 + ntl*8;
            stcs2(p0, c[mt][ntl][0], c[mt][ntl][1]);
            stcs2(p1, c[mt][ntl][2], c[mt][ntl][3]);
        }
    }
}

// ===========================================================================
extern "C" void kernel_launch(void* const* d_in, const int* in_sizes, int n_in,
                              void* d_out, int out_size) {
    const float* x = (const float*)d_in[0];   // [65536, 512]
    const float* v = (const float*)d_in[1];   // [514, 512, 1]
    float* out = (float*)d_out;               // [65536, 512]

    cudaFuncSetAttribute(gemm_mma_kernel, cudaFuncAttributeMaxDynamicSharedMemorySize, GEMM_SMEM);

    cvt_c_kernel<<<CVT_BLOCKS + NV + PAIR_BLOCKS, 256>>>(x, v);
    build_R_kernel<<<64, 256>>>(v);
    dim3 grid(4, MROWS / 128);
    gemm_mma_kernel<<<grid, 256, GEMM_SMEM>>>(out);
}

// round 13
// speedup vs baseline: 1.4051x; 1.0703x over previous
#include <cuda_runtime.h>
#include <cuda_fp16.h>
#include <cstdint>

#define NV    514
#define SDIM  512
#define MROWS 65536
#define EPSF  1e-16f

// ---------------------------------------------------------------------------
// Device scratch.
// g_B: R^T rows as fp16, PRE-SWIZZLED SMEM tile images:
//      [ntile(4)][chunk(8)] x 16384 B; each = 128(n) x 64(k) fp16, SW128.
// g_X: x converted to fp16, row-major [65536][512].
// g_P: pairwise reflector dots (quad Gram terms + tail pair).
// ---------------------------------------------------------------------------
__device__ __align__(16) unsigned char g_B[4 * 8 * 16384];
__device__ __align__(16) __half g_X[(size_t)MROWS * SDIM];
__device__ float g_c[NV];
__device__ float g_P[769];

#define SW128(b) ((b) ^ (((b) >> 3) & 0x70))
#define PAIR_DOTS 769
#define PAIR_BLOCKS 97
#define CVT_BLOCKS 8192
#define BR_BLOCKS 64

__device__ __forceinline__ uint32_t smem_u32(const void* p) {
    uint32_t a;
    asm("{ .reg .u64 t; cvta.to.shared.u64 t, %1; cvt.u32.u64 %0, t; }"
        : "=r"(a) : "l"(p));
    return a;
}
__device__ __forceinline__ void cpasync16(uint32_t dst, const void* src) {
    asm volatile("cp.async.cg.shared.global [%0], [%1], 16;"
        :: "r"(dst), "l"(src) : "memory");
}
#define CP_COMMIT() asm volatile("cp.async.commit_group;" ::: "memory")
#define CP_WAIT(n)  asm volatile("cp.async.wait_group %0;" :: "n"(n) : "memory")

// ===========================================================================
// Kernel 1 (small, all-parallel): c_k | quad pairwise dots
// ===========================================================================
__global__ __launch_bounds__(256) void c_pair_kernel(const float* __restrict__ v) {
    if (blockIdx.x < NV) {
        const int k = blockIdx.x;
        const int t = threadIdx.x;
        const float2 e = ((const float2*)(v + k * SDIM))[t];
        float s = fmaf(e.x, e.x, e.y * e.y);
        #pragma unroll
        for (int o = 16; o > 0; o >>= 1) s += __shfl_xor_sync(0xffffffffu, s, o);
        __shared__ float red[8];
        if ((t & 31) == 0) red[t >> 5] = s;
        __syncthreads();
        if (t == 0) {
            float tot = 0.f;
            #pragma unroll
            for (int i = 0; i < 8; ++i) tot += red[i];
            g_c[k] = 2.0f / (tot + EPSF);
        }
        return;
    }
    const int pb = blockIdx.x - NV;
    const int w = threadIdx.x >> 5;
    const int lane = threadIdx.x & 31;
    const int D = pb * 8 + w;
    if (D >= PAIR_DOTS) return;
    int ka, kb;
    if (D == 768) { ka = 513; kb = 512; }
    else {
        const int iq = D / 6, rr = D % 6;
        const int i_of[6] = {1, 2, 2, 3, 3, 3};
        const int j_of[6] = {0, 0, 1, 0, 1, 2};
        ka = 4 * iq + i_of[rr];
        kb = 4 * iq + j_of[rr];
    }
    const float4* pa = (const float4*)(v + (size_t)ka * SDIM);
    const float4* pc = (const float4*)(v + (size_t)kb * SDIM);
    float s = 0.f;
    #pragma unroll
    for (int m = 0; m < 4; ++m) {
        float4 fa = pa[m * 32 + lane];
        float4 fb = pc[m * 32 + lane];
        s = fmaf(fa.x, fb.x, s); s = fmaf(fa.y, fb.y, s);
        s = fmaf(fa.z, fb.z, s); s = fmaf(fa.w, fb.w, s);
    }
    #pragma unroll
    for (int o = 16; o > 0; o >>= 1) s += __shfl_xor_sync(0xffffffffu, s, o);
    if (lane == 0) g_P[D] = s;
}

// ===========================================================================
// Kernel 2 (FUSED): blocks [0,64) build_R (cp.async-pipelined v windows);
//                   blocks [64,64+8192) convert x fp32 -> fp16 into g_X.
// build_R: window-4 block Householder, one warp per column. Reflector data
// staged CTA-wide through smem with a 4-deep cp.async pipeline so DRAM/L2
// contention from the converter blocks cannot stall the serial chain.
// ===========================================================================
__global__ __launch_bounds__(256) void prep_kernel(const float* __restrict__ x,
                                                   const float* __restrict__ v) {
    __shared__ float sc[NV];
    __shared__ float sp[PAIR_DOTS];
    __shared__ __align__(16) float vbuf[4][4 * SDIM];   // 4 stages x 8KB

    if (blockIdx.x >= BR_BLOCKS) {
        // ---------------- convert x -> fp16 ----------------
        const size_t g = ((size_t)(blockIdx.x - BR_BLOCKS) * 256 + threadIdx.x) * 16;
        const float4* src = (const float4*)(x + g);
        float4 f0 = src[0], f1 = src[1], f2 = src[2], f3 = src[3];
        __half2 h[8];
        h[0] = __floats2half2_rn(f0.x, f0.y); h[1] = __floats2half2_rn(f0.z, f0.w);
        h[2] = __floats2half2_rn(f1.x, f1.y); h[3] = __floats2half2_rn(f1.z, f1.w);
        h[4] = __floats2half2_rn(f2.x, f2.y); h[5] = __floats2half2_rn(f2.z, f2.w);
        h[6] = __floats2half2_rn(f3.x, f3.y); h[7] = __floats2half2_rn(f3.z, f3.w);
        uint4* dst = (uint4*)(g_X + g);
        dst[0] = make_uint4(*(uint32_t*)&h[0], *(uint32_t*)&h[1],
                            *(uint32_t*)&h[2], *(uint32_t*)&h[3]);
        dst[1] = make_uint4(*(uint32_t*)&h[4], *(uint32_t*)&h[5],
                            *(uint32_t*)&h[6], *(uint32_t*)&h[7]);
        return;
    }

    // ---------------- build_R ----------------
    for (int i = threadIdx.x; i < NV; i += blockDim.x) sc[i] = g_c[i];
    for (int i = threadIdx.x; i < PAIR_DOTS; i += blockDim.x) sp[i] = g_P[i];

    const int lane = threadIdx.x & 31;
    const int j = blockIdx.x * 8 + (threadIdx.x >> 5);   // column 0..511

    const uint32_t vb0 = smem_u32(&vbuf[0][0]);
    auto fill = [&](int w) {
        const char* src = (const char*)(v + (size_t)w * 4 * SDIM) + threadIdx.x * 16;
        const uint32_t dst = vb0 + (uint32_t)(w & 3) * 8192u + threadIdx.x * 16;
        cpasync16(dst, src);
        cpasync16(dst + 4096, src + 4096);
        CP_COMMIT();
    };
    fill(0); fill(1); fill(2);

    float r[16];
    #pragma unroll
    for (int i = 0; i < 16; ++i) r[i] = 0.f;
    {
        const int m = j >> 7;
        if (lane == ((j & 127) >> 2)) r[m * 4 + (j & 3)] = 1.0f;
    }
    __syncthreads();   // sc/sp visible

    float a[4][16];
    for (int w = 0; w < 128; ++w) {
        if (w < 126)      { CP_WAIT(2); }
        else if (w == 126){ CP_WAIT(1); }
        else              { CP_WAIT(0); }
        __syncthreads();                 // window w data CTA-visible; stage (w+3)%4 free
        if (w < 125) fill(w + 3);

        // load window vectors from smem stage
        const float4* vs = (const float4*)&vbuf[w & 3][0];
        #pragma unroll
        for (int i = 0; i < 4; ++i)
            #pragma unroll
            for (int m = 0; m < 4; ++m) {
                float4 t = vs[i * 128 + m * 32 + lane];
                a[i][m*4+0]=t.x; a[i][m*4+1]=t.y; a[i][m*4+2]=t.z; a[i][m*4+3]=t.w;
            }

        const int k0 = w * 4;
        float dA[4], dB[4];
        #pragma unroll
        for (int i = 0; i < 4; ++i) { dA[i] = 0.f; dB[i] = 0.f; }
        #pragma unroll
        for (int e = 0; e < 16; e += 2) {
            #pragma unroll
            for (int i = 0; i < 4; ++i) {
                dA[i] = fmaf(a[i][e],   r[e],   dA[i]);
                dB[i] = fmaf(a[i][e+1], r[e+1], dB[i]);
            }
        }
        float d0 = dA[0]+dB[0], d1 = dA[1]+dB[1], d2 = dA[2]+dB[2], d3 = dA[3]+dB[3];
        #pragma unroll
        for (int o = 16; o > 0; o >>= 1) {
            d0 += __shfl_xor_sync(0xffffffffu, d0, o);
            d1 += __shfl_xor_sync(0xffffffffu, d1, o);
            d2 += __shfl_xor_sync(0xffffffffu, d2, o);
            d3 += __shfl_xor_sync(0xffffffffu, d3, o);
        }
        const float* P = sp + w * 6;
        const float t0 = d0 * sc[k0];
        const float t1 = fmaf(-t0, P[0], d1) * sc[k0+1];
        const float t2 = fmaf(-t1, P[2], fmaf(-t0, P[1], d2)) * sc[k0+2];
        const float t3 = fmaf(-t2, P[5], fmaf(-t1, P[4], fmaf(-t0, P[3], d3))) * sc[k0+3];
        #pragma unroll
        for (int e = 0; e < 16; ++e)
            r[e] = fmaf(-t3, a[3][e],
                   fmaf(-t2, a[2][e],
                   fmaf(-t1, a[1][e],
                   fmaf(-t0, a[0][e], r[e]))));
    }

    {   // tail: reflectors 512, 513 (direct global loads; chain is over)
        const float4* v4 = (const float4*)v;
        #pragma unroll
        for (int i = 0; i < 2; ++i)
            #pragma unroll
            for (int m = 0; m < 4; ++m) {
                float4 t = v4[(size_t)(512 + i) * 128 + m * 32 + lane];
                a[i][m*4+0]=t.x; a[i][m*4+1]=t.y; a[i][m*4+2]=t.z; a[i][m*4+3]=t.w;
            }
        float dA0=0.f, dB0=0.f, dA1=0.f, dB1=0.f;
        #pragma unroll
        for (int e = 0; e < 16; e += 2) {
            dA0 = fmaf(a[0][e],   r[e],   dA0);
            dB0 = fmaf(a[0][e+1], r[e+1], dB0);
            dA1 = fmaf(a[1][e],   r[e],   dA1);
            dB1 = fmaf(a[1][e+1], r[e+1], dB1);
        }
        float d = dA0 + dB0, p = dA1 + dB1;
        #pragma unroll
        for (int o = 16; o > 0; o >>= 1) {
            d += __shfl_xor_sync(0xffffffffu, d, o);
            p += __shfl_xor_sync(0xffffffffu, p, o);
        }
        const float q  = sp[768];
        const float t0 = d * sc[512];
        const float t1 = fmaf(-t0, q, p) * sc[513];
        #pragma unroll
        for (int e = 0; e < 16; ++e)
            r[e] = fmaf(-t1, a[1][e], fmaf(-t0, a[0][e], r[e]));
    }

    // store row j of R^T as fp16, pre-swizzled, 4 n-tiles of 128
    const int ntile = j >> 7;
    const unsigned rowb = (unsigned)(j & 127) * 128u;
    #pragma unroll
    for (int m = 0; m < 4; ++m) {
        const int k0 = m * 128 + lane * 4;
        const int chunk = k0 >> 6;
        const unsigned off = rowb + (unsigned)((k0 & 63) * 2);
        const unsigned sw = SW128(off);
        __half2 p0 = __floats2half2_rn(r[m*4+0], r[m*4+1]);
        __half2 p1 = __floats2half2_rn(r[m*4+2], r[m*4+3]);
        uint2 H = make_uint2(*(uint32_t*)&p0, *(uint32_t*)&p1);
        *(uint2*)(g_B + (((size_t)ntile*8 + chunk) * 16384) + sw) = H;
    }
}

// ===========================================================================
// Kernel 3: out = x @ R via mma.sync fp16 (fp32 acc), pure cp.async pipeline.
// CTA 128x128, 8 warps (4m x 2n), warp 32x64, K-chunk 64, 3 stages,
// 2 CTAs/SM, one __syncthreads per mainloop iteration.  (R8-exact)
// ===========================================================================
#define A_OFF 0
#define B_OFF 16384
#define STAGE_BYTES 32768
#define NSTAGE 3
#define GEMM_SMEM (1024 + NSTAGE * STAGE_BYTES)

__device__ __forceinline__ void ldsm4(uint32_t* r, uint32_t addr) {
    asm volatile("ldmatrix.sync.aligned.m8n8.x4.shared.b16 {%0,%1,%2,%3}, [%4];"
        : "=r"(r[0]), "=r"(r[1]), "=r"(r[2]), "=r"(r[3]) : "r"(addr));
}
__device__ __forceinline__ void mma16816(float* c, const uint32_t* a,
                                         uint32_t b0, uint32_t b1) {
    asm volatile(
        "mma.sync.aligned.m16n8k16.row.col.f32.f16.f16.f32 "
        "{%0,%1,%2,%3}, {%4,%5,%6,%7}, {%8,%9}, {%0,%1,%2,%3};"
        : "+f"(c[0]), "+f"(c[1]), "+f"(c[2]), "+f"(c[3])
        : "r"(a[0]), "r"(a[1]), "r"(a[2]), "r"(a[3]), "r"(b0), "r"(b1));
}

__global__ __launch_bounds__(256, 2) void gemm_mma_kernel(float* __restrict__ out) {
    extern __shared__ char dsm[];
    char* smp = (char*)(((uintptr_t)dsm + 1023) & ~(uintptr_t)1023);
    const uint32_t sb = smem_u32(smp);

    const int tid = threadIdx.x;
    const int wid = tid >> 5;
    const int lane = tid & 31;
    const int wm = wid & 3;          // m offset wm*32
    const int wn = wid >> 2;         // n offset wn*64
    const int nt = blockIdx.x;       // 0..3
    const int bm = blockIdx.y << 7;
    const int bn = nt << 7;

    const int arow = tid >> 1;
    const int ahalf = (tid & 1) * 64;
    const __half* aRowPtr = g_X + (size_t)(bm + arow) * SDIM;
    const unsigned aBase = (unsigned)arow * 128u + (unsigned)ahalf;

    float c[2][8][4];
    #pragma unroll
    for (int i = 0; i < 2; ++i)
        #pragma unroll
        for (int jj = 0; jj < 8; ++jj)
            #pragma unroll
            for (int q = 0; q < 4; ++q) c[i][jj][q] = 0.f;

    auto fill_stage = [&](int kc) {
        const uint32_t st = sb + (kc % NSTAGE) * STAGE_BYTES;
        const char* aSrc = (const char*)(aRowPtr + kc * 64) + ahalf;
        #pragma unroll
        for (int i = 0; i < 4; ++i)
            cpasync16(st + A_OFF + SW128(aBase + i * 16u), aSrc + i * 16);
        const char* bSrc = (const char*)(g_B + (((size_t)nt * 8 + kc) * 16384)) + tid * 16;
        #pragma unroll
        for (int i = 0; i < 4; ++i)
            cpasync16(st + B_OFF + tid * 16 + i * 4096, bSrc + i * 4096);
        CP_COMMIT();
    };

    fill_stage(0);
    fill_stage(1);

    const int la = lane & 15;
    const int lh = lane >> 4;

    for (int kc = 0; kc < 8; ++kc) {
        if (kc == 7) { CP_WAIT(0); } else { CP_WAIT(1); }
        __syncthreads();   // stage kc visible; stage (kc-1)%3 fully consumed
        if (kc < 6) fill_stage(kc + 2);

        const uint32_t st = sb + (kc % NSTAGE) * STAGE_BYTES;
        #pragma unroll
        for (int ks = 0; ks < 4; ++ks) {
            uint32_t af[2][4], bf[4][4];
            #pragma unroll
            for (int mt = 0; mt < 2; ++mt) {
                const unsigned off = (unsigned)(wm*32 + mt*16 + la) * 128u
                                   + (unsigned)((lh*8 + ks*16) * 2);
                ldsm4(af[mt], st + A_OFF + SW128(off));
            }
            #pragma unroll
            for (int np = 0; np < 4; ++np) {
                const unsigned off = (unsigned)(wn*64 + np*16 + la) * 128u
                                   + (unsigned)((lh*8 + ks*16) * 2);
                ldsm4(bf[np], st + B_OFF + SW128(off));
            }
            #pragma unroll
            for (int mt = 0; mt < 2; ++mt)
                #pragma unroll
                for (int np = 0; np < 4; ++np) {
                    mma16816(c[mt][2*np],   af[mt], bf[np][0], bf[np][2]);
                    mma16816(c[mt][2*np+1], af[mt], bf[np][1], bf[np][3]);
                }
        }
    }

    // epilogue
    const int r0 = bm + wm * 32 + (lane >> 2);
    const int c0 = bn + wn * 64 + (lane & 3) * 2;
    #pragma unroll
    for (int mt = 0; mt < 2; ++mt) {
        #pragma unroll
        for (int ntl = 0; ntl < 8; ++ntl) {
            float* p0 = out + (size_t)(r0 + mt*16)     * SDIM + c0 + ntl*8;
            float* p1 = out + (size_t)(r0 + mt*16 + 8) * SDIM + c0 + ntl*8;
            *(float2*)p0 = make_float2(c[mt][ntl][0], c[mt][ntl][1]);
            *(float2*)p1 = make_float2(c[mt][ntl][2], c[mt][ntl][3]);
        }
    }
}

// ===========================================================================
extern "C" void kernel_launch(void* const* d_in, const int* in_sizes, int n_in,
                              void* d_out, int out_size) {
    const float* x = (const float*)d_in[0];   // [65536, 512]
    const float* v = (const float*)d_in[1];   // [514, 512, 1]
    float* out = (float*)d_out;               // [65536, 512]

    cudaFuncSetAttribute(gemm_mma_kernel, cudaFuncAttributeMaxDynamicSharedMemorySize, GEMM_SMEM);

    c_pair_kernel<<<NV + PAIR_BLOCKS, 256>>>(v);
    prep_kernel<<<BR_BLOCKS + CVT_BLOCKS, 256>>>(x, v);
    dim3 grid(4, MROWS / 128);
    gemm_mma_kernel<<<grid, 256, GEMM_SMEM>>>(out);
}

// round 14
// speedup vs baseline: 1.4086x; 1.0025x over previous
#include <cuda_runtime.h>
#include <cuda_fp16.h>
#include <cstdint>

#define NV    514
#define SDIM  512
#define MROWS 65536
#define EPSF  1e-16f

// ---------------------------------------------------------------------------
// Device scratch.
// g_B: R^T rows as fp16, PRE-SWIZZLED SMEM tile images:
//      [ntile(4)][chunk(8)] x 16384 B; each = 128(n) x 64(k) fp16, SW128.
// g_X: x converted to fp16, row-major [65536][512].
// g_P: pairwise reflector dots (quad Gram terms + tail pair).
// ---------------------------------------------------------------------------
__device__ __align__(16) unsigned char g_B[4 * 8 * 16384];
__device__ __align__(16) __half g_X[(size_t)MROWS * SDIM];
__device__ float g_c[NV];
__device__ float g_P[769];

#define SW128(b) ((b) ^ (((b) >> 3) & 0x70))
#define PAIR_DOTS 769
#define TOTAL_DOTS (NV + PAIR_DOTS)          /* 1283 warp-jobs */
#define DOT_BLOCKS ((TOTAL_DOTS + 7) / 8)    /* 161 */
#define CVT_BLOCKS 8192
#define BR_BLOCKS 64

__device__ __forceinline__ uint32_t smem_u32(const void* p) {
    uint32_t a;
    asm("{ .reg .u64 t; cvta.to.shared.u64 t, %1; cvt.u32.u64 %0, t; }"
        : "=r"(a) : "l"(p));
    return a;
}
__device__ __forceinline__ void cpasync16(uint32_t dst, const void* src) {
    asm volatile("cp.async.cg.shared.global [%0], [%1], 16;"
        :: "r"(dst), "l"(src) : "memory");
}
#define CP_COMMIT() asm volatile("cp.async.commit_group;" ::: "memory")
#define CP_WAIT(n)  asm volatile("cp.async.wait_group %0;" :: "n"(n) : "memory")

// ===========================================================================
// Kernel 1: all dots, one WARP per dot. Jobs 0..513 -> c_k; 514.. -> pairs.
// ===========================================================================
__global__ __launch_bounds__(256) void c_pair_kernel(const float* __restrict__ v) {
    const int w = threadIdx.x >> 5;
    const int lane = threadIdx.x & 31;
    const int D = blockIdx.x * 8 + w;
    if (D >= TOTAL_DOTS) return;

    int ka, kb;
    if (D < NV) { ka = D; kb = D; }
    else {
        const int E = D - NV;
        if (E == 768) { ka = 513; kb = 512; }
        else {
            const int iq = E / 6, rr = E % 6;
            const int i_of[6] = {1, 2, 2, 3, 3, 3};
            const int j_of[6] = {0, 0, 1, 0, 1, 2};
            ka = 4 * iq + i_of[rr];
            kb = 4 * iq + j_of[rr];
        }
    }
    const float4* pa = (const float4*)(v + (size_t)ka * SDIM);
    const float4* pc = (const float4*)(v + (size_t)kb * SDIM);
    float s = 0.f;
    #pragma unroll
    for (int m = 0; m < 4; ++m) {
        float4 fa = pa[m * 32 + lane];
        float4 fb = pc[m * 32 + lane];
        s = fmaf(fa.x, fb.x, s); s = fmaf(fa.y, fb.y, s);
        s = fmaf(fa.z, fb.z, s); s = fmaf(fa.w, fb.w, s);
    }
    #pragma unroll
    for (int o = 16; o > 0; o >>= 1) s += __shfl_xor_sync(0xffffffffu, s, o);
    if (lane == 0) {
        if (D < NV) g_c[D] = 2.0f / (s + EPSF);
        else        g_P[D - NV] = s;
    }
}

// ===========================================================================
// Kernel 2 (FUSED): blocks [0,64) build_R (cp.async-pipelined v windows);
//                   blocks [64,64+8192) convert x fp32 -> fp16 into g_X.
// ===========================================================================
__global__ __launch_bounds__(256) void prep_kernel(const float* __restrict__ x,
                                                   const float* __restrict__ v) {
    __shared__ float sc[NV];
    __shared__ float sp[PAIR_DOTS];
    __shared__ __align__(16) float vbuf[4][4 * SDIM];   // 4 stages x 8KB

    if (blockIdx.x >= BR_BLOCKS) {
        // ---------------- convert x -> fp16 ----------------
        const size_t g = ((size_t)(blockIdx.x - BR_BLOCKS) * 256 + threadIdx.x) * 16;
        const float4* src = (const float4*)(x + g);
        float4 f0 = src[0], f1 = src[1], f2 = src[2], f3 = src[3];
        __half2 h[8];
        h[0] = __floats2half2_rn(f0.x, f0.y); h[1] = __floats2half2_rn(f0.z, f0.w);
        h[2] = __floats2half2_rn(f1.x, f1.y); h[3] = __floats2half2_rn(f1.z, f1.w);
        h[4] = __floats2half2_rn(f2.x, f2.y); h[5] = __floats2half2_rn(f2.z, f2.w);
        h[6] = __floats2half2_rn(f3.x, f3.y); h[7] = __floats2half2_rn(f3.z, f3.w);
        uint4* dst = (uint4*)(g_X + g);
        dst[0] = make_uint4(*(uint32_t*)&h[0], *(uint32_t*)&h[1],
                            *(uint32_t*)&h[2], *(uint32_t*)&h[3]);
        dst[1] = make_uint4(*(uint32_t*)&h[4], *(uint32_t*)&h[5],
                            *(uint32_t*)&h[6], *(uint32_t*)&h[7]);
        return;
    }

    // ---------------- build_R ----------------
    for (int i = threadIdx.x; i < NV; i += blockDim.x) sc[i] = g_c[i];
    for (int i = threadIdx.x; i < PAIR_DOTS; i += blockDim.x) sp[i] = g_P[i];

    const int lane = threadIdx.x & 31;
    const int j = blockIdx.x * 8 + (threadIdx.x >> 5);   // column 0..511

    const uint32_t vb0 = smem_u32(&vbuf[0][0]);
    auto fill = [&](int w) {
        const char* src = (const char*)(v + (size_t)w * 4 * SDIM) + threadIdx.x * 16;
        const uint32_t dst = vb0 + (uint32_t)(w & 3) * 8192u + threadIdx.x * 16;
        cpasync16(dst, src);
        cpasync16(dst + 4096, src + 4096);
        CP_COMMIT();
    };
    fill(0); fill(1); fill(2);

    float r[16];
    #pragma unroll
    for (int i = 0; i < 16; ++i) r[i] = 0.f;
    {
        const int m = j >> 7;
        if (lane == ((j & 127) >> 2)) r[m * 4 + (j & 3)] = 1.0f;
    }
    __syncthreads();   // sc/sp visible

    float a[4][16];
    for (int w = 0; w < 128; ++w) {
        if (w < 126)      { CP_WAIT(2); }
        else if (w == 126){ CP_WAIT(1); }
        else              { CP_WAIT(0); }
        __syncthreads();                 // window w CTA-visible; stage (w+3)%4 free
        if (w < 125) fill(w + 3);

        const float4* vs = (const float4*)&vbuf[w & 3][0];
        #pragma unroll
        for (int i = 0; i < 4; ++i)
            #pragma unroll
            for (int m = 0; m < 4; ++m) {
                float4 t = vs[i * 128 + m * 32 + lane];
                a[i][m*4+0]=t.x; a[i][m*4+1]=t.y; a[i][m*4+2]=t.z; a[i][m*4+3]=t.w;
            }

        const int k0 = w * 4;
        float dA[4], dB[4];
        #pragma unroll
        for (int i = 0; i < 4; ++i) { dA[i] = 0.f; dB[i] = 0.f; }
        #pragma unroll
        for (int e = 0; e < 16; e += 2) {
            #pragma unroll
            for (int i = 0; i < 4; ++i) {
                dA[i] = fmaf(a[i][e],   r[e],   dA[i]);
                dB[i] = fmaf(a[i][e+1], r[e+1], dB[i]);
            }
        }
        float d0 = dA[0]+dB[0], d1 = dA[1]+dB[1], d2 = dA[2]+dB[2], d3 = dA[3]+dB[3];
        #pragma unroll
        for (int o = 16; o > 0; o >>= 1) {
            d0 += __shfl_xor_sync(0xffffffffu, d0, o);
            d1 += __shfl_xor_sync(0xffffffffu, d1, o);
            d2 += __shfl_xor_sync(0xffffffffu, d2, o);
            d3 += __shfl_xor_sync(0xffffffffu, d3, o);
        }
        const float* P = sp + w * 6;
        const float t0 = d0 * sc[k0];
        const float t1 = fmaf(-t0, P[0], d1) * sc[k0+1];
        const float t2 = fmaf(-t1, P[2], fmaf(-t0, P[1], d2)) * sc[k0+2];
        const float t3 = fmaf(-t2, P[5], fmaf(-t1, P[4], fmaf(-t0, P[3], d3))) * sc[k0+3];
        #pragma unroll
        for (int e = 0; e < 16; ++e)
            r[e] = fmaf(-t3, a[3][e],
                   fmaf(-t2, a[2][e],
                   fmaf(-t1, a[1][e],
                   fmaf(-t0, a[0][e], r[e]))));
    }

    {   // tail: reflectors 512, 513 (direct global loads; chain is over)
        const float4* v4 = (const float4*)v;
        #pragma unroll
        for (int i = 0; i < 2; ++i)
            #pragma unroll
            for (int m = 0; m < 4; ++m) {
                float4 t = v4[(size_t)(512 + i) * 128 + m * 32 + lane];
                a[i][m*4+0]=t.x; a[i][m*4+1]=t.y; a[i][m*4+2]=t.z; a[i][m*4+3]=t.w;
            }
        float dA0=0.f, dB0=0.f, dA1=0.f, dB1=0.f;
        #pragma unroll
        for (int e = 0; e < 16; e += 2) {
            dA0 = fmaf(a[0][e],   r[e],   dA0);
            dB0 = fmaf(a[0][e+1], r[e+1], dB0);
            dA1 = fmaf(a[1][e],   r[e],   dA1);
            dB1 = fmaf(a[1][e+1], r[e+1], dB1);
        }
        float d = dA0 + dB0, p = dA1 + dB1;
        #pragma unroll
        for (int o = 16; o > 0; o >>= 1) {
            d += __shfl_xor_sync(0xffffffffu, d, o);
            p += __shfl_xor_sync(0xffffffffu, p, o);
        }
        const float q  = sp[768];
        const float t0 = d * sc[512];
        const float t1 = fmaf(-t0, q, p) * sc[513];
        #pragma unroll
        for (int e = 0; e < 16; ++e)
            r[e] = fmaf(-t1, a[1][e], fmaf(-t0, a[0][e], r[e]));
    }

    // store row j of R^T as fp16, pre-swizzled, 4 n-tiles of 128
    const int ntile = j >> 7;
    const unsigned rowb = (unsigned)(j & 127) * 128u;
    #pragma unroll
    for (int m = 0; m < 4; ++m) {
        const int k0 = m * 128 + lane * 4;
        const int chunk = k0 >> 6;
        const unsigned off = rowb + (unsigned)((k0 & 63) * 2);
        const unsigned sw = SW128(off);
        __half2 p0 = __floats2half2_rn(r[m*4+0], r[m*4+1]);
        __half2 p1 = __floats2half2_rn(r[m*4+2], r[m*4+3]);
        uint2 H = make_uint2(*(uint32_t*)&p0, *(uint32_t*)&p1);
        *(uint2*)(g_B + (((size_t)ntile*8 + chunk) * 16384) + sw) = H;
    }
}

// ===========================================================================
// Kernel 3: out = x @ R via mma.sync fp16 (fp32 acc), pure cp.async pipeline.
// CTA 128x128, 8 warps (4m x 2n), warp 32x64, K-chunk 64, 3 stages,
// 2 CTAs/SM, one __syncthreads per mainloop iteration.  (R8/R13-exact)
// ===========================================================================
#define A_OFF 0
#define B_OFF 16384
#define STAGE_BYTES 32768
#define NSTAGE 3
#define GEMM_SMEM (1024 + NSTAGE * STAGE_BYTES)

__device__ __forceinline__ void ldsm4(uint32_t* r, uint32_t addr) {
    asm volatile("ldmatrix.sync.aligned.m8n8.x4.shared.b16 {%0,%1,%2,%3}, [%4];"
        : "=r"(r[0]), "=r"(r[1]), "=r"(r[2]), "=r"(r[3]) : "r"(addr));
}
__device__ __forceinline__ void mma16816(float* c, const uint32_t* a,
                                         uint32_t b0, uint32_t b1) {
    asm volatile(
        "mma.sync.aligned.m16n8k16.row.col.f32.f16.f16.f32 "
        "{%0,%1,%2,%3}, {%4,%5,%6,%7}, {%8,%9}, {%0,%1,%2,%3};"
        : "+f"(c[0]), "+f"(c[1]), "+f"(c[2]), "+f"(c[3])
        : "r"(a[0]), "r"(a[1]), "r"(a[2]), "r"(a[3]), "r"(b0), "r"(b1));
}

__global__ __launch_bounds__(256, 2) void gemm_mma_kernel(float* __restrict__ out) {
    extern __shared__ char dsm[];
    char* smp = (char*)(((uintptr_t)dsm + 1023) & ~(uintptr_t)1023);
    const uint32_t sb = smem_u32(smp);

    const int tid = threadIdx.x;
    const int wid = tid >> 5;
    const int lane = tid & 31;
    const int wm = wid & 3;          // m offset wm*32
    const int wn = wid >> 2;         // n offset wn*64
    const int nt = blockIdx.x;       // 0..3
    const int bm = blockIdx.y << 7;
    const int bn = nt << 7;

    const int arow = tid >> 1;
    const int ahalf = (tid & 1) * 64;
    const __half* aRowPtr = g_X + (size_t)(bm + arow) * SDIM;
    const unsigned aBase = (unsigned)arow * 128u + (unsigned)ahalf;

    float c[2][8][4];
    #pragma unroll
    for (int i = 0; i < 2; ++i)
        #pragma unroll
        for (int jj = 0; jj < 8; ++jj)
            #pragma unroll
            for (int q = 0; q < 4; ++q) c[i][jj][q] = 0.f;

    auto fill_stage = [&](int kc) {
        const uint32_t st = sb + (kc % NSTAGE) * STAGE_BYTES;
        const char* aSrc = (const char*)(aRowPtr + kc * 64) + ahalf;
        #pragma unroll
        for (int i = 0; i < 4; ++i)
            cpasync16(st + A_OFF + SW128(aBase + i * 16u), aSrc + i * 16);
        const char* bSrc = (const char*)(g_B + (((size_t)nt * 8 + kc) * 16384)) + tid * 16;
        #pragma unroll
        for (int i = 0; i < 4; ++i)
            cpasync16(st + B_OFF + tid * 16 + i * 4096, bSrc + i * 4096);
        CP_COMMIT();
    };

    fill_stage(0);
    fill_stage(1);

    const int la = lane & 15;
    const int lh = lane >> 4;

    for (int kc = 0; kc < 8; ++kc) {
        if (kc == 7) { CP_WAIT(0); } else { CP_WAIT(1); }
        __syncthreads();   // stage kc visible; stage (kc-1)%3 fully consumed
        if (kc < 6) fill_stage(kc + 2);

        const uint32_t st = sb + (kc % NSTAGE) * STAGE_BYTES;
        #pragma unroll
        for (int ks = 0; ks < 4; ++ks) {
            uint32_t af[2][4], bf[4][4];
            #pragma unroll
            for (int mt = 0; mt < 2; ++mt) {
                const unsigned off = (unsigned)(wm*32 + mt*16 + la) * 128u
                                   + (unsigned)((lh*8 + ks*16) * 2);
                ldsm4(af[mt], st + A_OFF + SW128(off));
            }
            #pragma unroll
            for (int np = 0; np < 4; ++np) {
                const unsigned off = (unsigned)(wn*64 + np*16 + la) * 128u
                                   + (unsigned)((lh*8 + ks*16) * 2);
                ldsm4(bf[np], st + B_OFF + SW128(off));
            }
            #pragma unroll
            for (int mt = 0; mt < 2; ++mt)
                #pragma unroll
                for (int np = 0; np < 4; ++np) {
                    mma16816(c[mt][2*np],   af[mt], bf[np][0], bf[np][2]);
                    mma16816(c[mt][2*np+1], af[mt], bf[np][1], bf[np][3]);
                }
        }
    }

    // epilogue
    const int r0 = bm + wm * 32 + (lane >> 2);
    const int c0 = bn + wn * 64 + (lane & 3) * 2;
    #pragma unroll
    for (int mt = 0; mt < 2; ++mt) {
        #pragma unroll
        for (int ntl = 0; ntl < 8; ++ntl) {
            float* p0 = out + (size_t)(r0 + mt*16)     * SDIM + c0 + ntl*8;
            float* p1 = out + (size_t)(r0 + mt*16 + 8) * SDIM + c0 + ntl*8;
            *(float2*)p0 = make_float2(c[mt][ntl][0], c[mt][ntl][1]);
            *(float2*)p1 = make_float2(c[mt][ntl][2], c[mt][ntl][3]);
        }
    }
}

// ===========================================================================
extern "C" void kernel_launch(void* const* d_in, const int* in_sizes, int n_in,
                              void* d_out, int out_size) {
    const float* x = (const float*)d_in[0];   // [65536, 512]
    const float* v = (const float*)d_in[1];   // [514, 512, 1]
    float* out = (float*)d_out;               // [65536, 512]

    cudaFuncSetAttribute(gemm_mma_kernel, cudaFuncAttributeMaxDynamicSharedMemorySize, GEMM_SMEM);

    c_pair_kernel<<<DOT_BLOCKS, 256>>>(v);
    prep_kernel<<<BR_BLOCKS + CVT_BLOCKS, 256>>>(x, v);
    dim3 grid(4, MROWS / 128);
    gemm_mma_kernel<<<grid, 256, GEMM_SMEM>>>(out);
}